// round 13
// baseline (speedup 1.0000x reference)
#include <cuda_runtime.h>
#include <cuda_fp16.h>
#include <cstdint>
#include <cstddef>
#include <math.h>

// Problem constants
#define Dm   2048
#define Hh   32
#define DSs  64
#define KK   4
#define EPSf 1e-6f
#define NC   64            // scan chunks

// Max sizes (B=2, L=4096)
#define BL_MAX  8192
#define P_COLS  (3*Dm)   // 6144
#define NB_MAX  64       // B*H chains

// Scratch layout (in floats)
#define OFF_XNH    ((size_t)0)                               // half[BL*Dm]
#define OFF_XCH    (OFF_XNH + (size_t)BL_MAX*Dm/2)
#define OFF_MXH    (OFF_XCH + (size_t)BL_MAX*Dm/2)
#define OFF_PH     (OFF_MXH + (size_t)BL_MAX*Dm/2)           // half[BL*P_COLS]
#define OFF_GATEH  (OFF_PH  + (size_t)BL_MAX*P_COLS/2)       // half[BL*Dm]
#define OFF_SCANA  (OFF_GATEH + (size_t)BL_MAX*Dm/2)
#define OFF_SCANH  (OFF_SCANA + (size_t)NB_MAX*NC*DSs)
#define OFF_SCANI  (OFF_SCANH + (size_t)NB_MAX*NC*DSs)
#define OFF_PPH    (OFF_SCANI + (size_t)NB_MAX*NC*DSs)       // half[P_COLS*Dm]
#define OFF_GPH    (OFF_PPH + (size_t)P_COLS*Dm/2)
#define OFF_OPH    (OFF_GPH + (size_t)Dm*Dm/2)
#define SCRATCH_FLOATS (OFF_OPH + (size_t)Dm*Dm/2)

__device__ float g_scratch[SCRATCH_FLOATS];

// ---------------------------------------------------------------------------
// Helpers
// ---------------------------------------------------------------------------
__device__ __forceinline__ void mma_f16(float* c, const uint32_t* a, const uint32_t* b) {
    asm volatile(
        "mma.sync.aligned.m16n8k16.row.col.f32.f16.f16.f32 "
        "{%0,%1,%2,%3}, {%4,%5,%6,%7}, {%8,%9}, {%0,%1,%2,%3};\n"
        : "+f"(c[0]), "+f"(c[1]), "+f"(c[2]), "+f"(c[3])
        : "r"(a[0]), "r"(a[1]), "r"(a[2]), "r"(a[3]),
          "r"(b[0]), "r"(b[1]));
}

__device__ __forceinline__ void ldsm_x4(uint32_t* r, uint32_t addr) {
    asm volatile("ldmatrix.sync.aligned.m8n8.x4.shared.b16 {%0,%1,%2,%3}, [%4];"
        : "=r"(r[0]), "=r"(r[1]), "=r"(r[2]), "=r"(r[3]) : "r"(addr));
}

__device__ __forceinline__ void cp_async16(void* smem, const void* gmem) {
    uint32_t s = (uint32_t)__cvta_generic_to_shared(smem);
    asm volatile("cp.async.cg.shared.global [%0], [%1], 16;\n" :: "r"(s), "l"(gmem));
}

__device__ __forceinline__ float sigmoidf_(float v) {
    return 1.0f / (1.0f + __expf(-v));
}

__device__ __forceinline__ uint2 pack4h(float a, float b, float c, float d) {
    __half2 lo = __floats2half2_rn(a, b);
    __half2 hi = __floats2half2_rn(c, d);
    uint2 r;
    r.x = *(uint32_t*)&lo;
    r.y = *(uint32_t*)&hi;
    return r;
}

// ---------------------------------------------------------------------------
// Fused weight transpose + fp16 round for all three weights (z-indexed).
// ---------------------------------------------------------------------------
__global__ void transpose_half_all(const float* __restrict__ pp,
                                   const float* __restrict__ gp,
                                   const float* __restrict__ op,
                                   __half* __restrict__ ppT,
                                   __half* __restrict__ gpT,
                                   __half* __restrict__ opT) {
    const float* W;
    __half* WT;
    int N;
    if (blockIdx.z == 0)      { W = pp; WT = ppT; N = P_COLS; }
    else if (blockIdx.z == 1) { W = gp; WT = gpT; N = Dm; }
    else                      { W = op; WT = opT; N = Dm; }
    if (blockIdx.x * 32 >= N) return;

    __shared__ float t[32][33];
    int n0 = blockIdx.x * 32, k0 = blockIdx.y * 32;
    int tx = threadIdx.x, ty = threadIdx.y;
    #pragma unroll
    for (int i = 0; i < 4; i++)
        t[ty + 8*i][tx] = W[(size_t)(k0 + ty + 8*i) * N + n0 + tx];
    __syncthreads();
    int tid = ty * 32 + tx;
    int n_l = tid >> 3;
    int kq  = tid & 7;
    float a = t[kq*4 + 0][n_l];
    float b = t[kq*4 + 1][n_l];
    float c = t[kq*4 + 2][n_l];
    float d = t[kq*4 + 3][n_l];
    *(uint2*)&WT[(size_t)(n0 + n_l) * Dm + k0 + kq*4] = pack4h(a, b, c, d);
}

// ---------------------------------------------------------------------------
// RMSNorm (stores fp16 xn)
// ---------------------------------------------------------------------------
__global__ void rmsnorm_kernel(const float* __restrict__ x,
                               const float* __restrict__ w,
                               __half* __restrict__ xn) {
    size_t row = blockIdx.x;
    const float4* xr = (const float4*)(x + row * Dm);
    float4 v0 = xr[threadIdx.x];
    float4 v1 = xr[threadIdx.x + 256];
    float ss = v0.x*v0.x + v0.y*v0.y + v0.z*v0.z + v0.w*v0.w
             + v1.x*v1.x + v1.y*v1.y + v1.z*v1.z + v1.w*v1.w;
    #pragma unroll
    for (int o = 16; o > 0; o >>= 1) ss += __shfl_xor_sync(0xffffffffu, ss, o);
    __shared__ float red[8];
    if ((threadIdx.x & 31) == 0) red[threadIdx.x >> 5] = ss;
    __syncthreads();
    float tot = red[0] + red[1] + red[2] + red[3] + red[4] + red[5] + red[6] + red[7];
    float inv = rsqrtf(tot * (1.0f / Dm) + EPSf);

    const float4* wr = (const float4*)w;
    float4 w0 = wr[threadIdx.x];
    float4 w1 = wr[threadIdx.x + 256];
    uint2* orow = (uint2*)(xn + row * Dm);
    orow[threadIdx.x] = pack4h(v0.x * w0.x * inv, v0.y * w0.y * inv,
                               v0.z * w0.z * inv, v0.w * w0.w * inv);
    orow[threadIdx.x + 256] = pack4h(v1.x * w1.x * inv, v1.y * w1.y * inv,
                                     v1.z * w1.z * inv, v1.w * w1.w * inv);
}

// ---------------------------------------------------------------------------
// Causal depthwise conv (K=4) + SiLU (fp16 in, fp16 out; fp32 math)
// ---------------------------------------------------------------------------
__global__ void conv_silu_kernel(const __half* __restrict__ xn,
                                 const float* __restrict__ cw,
                                 const float* __restrict__ cb,
                                 __half* __restrict__ xc, int L) {
    int d  = blockIdx.x * 128 + threadIdx.x;
    int b  = blockIdx.z;
    int l0 = blockIdx.y * 256;
    float w0 = cw[d*KK + 0], w1 = cw[d*KK + 1], w2 = cw[d*KK + 2], w3 = cw[d*KK + 3];
    float bb = cb[d];
    const __half* base = xn + ((size_t)b * L) * Dm + d;
    __half* obase      = xc + ((size_t)b * L) * Dm + d;

    float xm3 = (l0 >= 3) ? __half2float(base[(size_t)(l0 - 3) * Dm]) : 0.0f;
    float xm2 = (l0 >= 2) ? __half2float(base[(size_t)(l0 - 2) * Dm]) : 0.0f;
    float xm1 = (l0 >= 1) ? __half2float(base[(size_t)(l0 - 1) * Dm]) : 0.0f;

    #pragma unroll 8
    for (int l = l0; l < l0 + 256; l++) {
        float xcur = __half2float(base[(size_t)l * Dm]);
        float acc = bb + w0 * xm3 + w1 * xm2 + w2 * xm1 + w3 * xcur;
        float sv = acc * sigmoidf_(acc);
        obase[(size_t)l * Dm] = __float2half_rn(sv);
        xm3 = xm2; xm2 = xm1; xm1 = xcur;
    }
}

// ---------------------------------------------------------------------------
// FP16 GEMM (fp32 accum): BM=128, BN=256, BK=64, warp tile 64x64.
//   MODE 0: +bias -> half out   MODE 1: sigmoid(+bias) -> half out
//   MODE 2: +bias+res -> float out
// 256 threads (8 warps: 2M x 4N), double-buffered cp.async, 1 CTA/SM.
// ---------------------------------------------------------------------------
#define FSTR 72                     // halves per SMEM row (72 mod 32 = 8)
#define A_TILE_HV (128 * FSTR)      // 9216 halves
#define B_TILE_HV (256 * FSTR)      // 18432 halves
#define STG_HV (A_TILE_HV + B_TILE_HV)
#define GEMM_SMEM_BYTES (2 * STG_HV * 2)   // 110592 B

template<int MODE>
__global__ __launch_bounds__(256, 1)
void gemm_fp16(const __half* __restrict__ A, const __half* __restrict__ BT,
               const float* __restrict__ bias, const float* __restrict__ res,
               void* __restrict__ Cout, int M, int N, int K) {
    extern __shared__ __half smh[];
    // stage s: A at s*STG_HV, B at s*STG_HV + A_TILE_HV

    int tid  = threadIdx.x;
    int wid  = tid >> 5;
    int lane = tid & 31;
    int wm = (wid & 1) * 64;        // warp M offset (0/64)
    int wn = (wid >> 1) * 64;       // warp N offset (0/64/128/192)
    int g = lane >> 2;
    int t = lane & 3;

    int bm = blockIdx.y * 128;
    int bn = blockIdx.x * 256;

    const __half* Aptr = A  + (size_t)bm * K;
    const __half* Bptr = BT + (size_t)bn * K;

    float acc[4][8][4];
    #pragma unroll
    for (int i = 0; i < 4; i++)
        #pragma unroll
        for (int j = 0; j < 8; j++)
            #pragma unroll
            for (int q = 0; q < 4; q++) acc[i][j][q] = 0.0f;

    // Loaders: 16B chunks; row = id>>3, colchunk = id&7
    int l_r = tid >> 3;            // 0..31
    int l_c = (tid & 7) * 8;       // 0..56 halves

    uint32_t smBase = (uint32_t)__cvta_generic_to_shared(&smh[0]);
    // A ldsm.x4: row = wm + mt*16 + (lane&15); col halves = (lane>>4)*8 + k16*16
    uint32_t a_off = (uint32_t)(((wm + (lane & 15)) * FSTR + ((lane >> 4) << 3)) * 2);
    // B ldsm.x4 (two n-tiles): row = wn + np*16 + (lane&7) + ((lane&16)?8:0);
    //                          col halves = (lane&8) + k16*16
    uint32_t b_off = (uint32_t)(((wn + (lane & 7) + ((lane >> 1) & 8)) * FSTR + (lane & 8)) * 2);

    int NK = K / 64;

    // Prologue: stage 0
    {
        #pragma unroll
        for (int i = 0; i < 4; i++) {
            int r = l_r + 32 * i;
            cp_async16(&smh[r * FSTR + l_c], Aptr + (size_t)r * K + l_c);
        }
        #pragma unroll
        for (int i = 0; i < 8; i++) {
            int r = l_r + 32 * i;
            cp_async16(&smh[A_TILE_HV + r * FSTR + l_c], Bptr + (size_t)r * K + l_c);
        }
        asm volatile("cp.async.commit_group;\n" ::);
    }

    for (int kt = 0; kt < NK; kt++) {
        int buf = kt & 1;
        if (kt + 1 < NK) {
            int k0 = (kt + 1) * 64;
            __half* nA = smh + (buf ^ 1) * STG_HV;
            __half* nB = nA + A_TILE_HV;
            #pragma unroll
            for (int i = 0; i < 4; i++) {
                int r = l_r + 32 * i;
                cp_async16(&nA[r * FSTR + l_c], Aptr + (size_t)r * K + k0 + l_c);
            }
            #pragma unroll
            for (int i = 0; i < 8; i++) {
                int r = l_r + 32 * i;
                cp_async16(&nB[r * FSTR + l_c], Bptr + (size_t)r * K + k0 + l_c);
            }
            asm volatile("cp.async.commit_group;\n" ::);
            asm volatile("cp.async.wait_group 1;\n" ::);
        } else {
            asm volatile("cp.async.wait_group 0;\n" ::);
        }
        __syncthreads();

        uint32_t aBase = smBase + (uint32_t)(buf * STG_HV * 2) + a_off;
        uint32_t bBase = smBase + (uint32_t)((buf * STG_HV + A_TILE_HV) * 2) + b_off;

        #pragma unroll
        for (int k16 = 0; k16 < 4; k16++) {
            uint32_t af[4][4], bf[8][2];
            #pragma unroll
            for (int mt = 0; mt < 4; mt++)
                ldsm_x4(af[mt], aBase + (uint32_t)(mt * 16 * FSTR * 2 + k16 * 32));
            #pragma unroll
            for (int np = 0; np < 4; np++) {
                uint32_t r4[4];
                ldsm_x4(r4, bBase + (uint32_t)(np * 16 * FSTR * 2 + k16 * 32));
                bf[2*np][0] = r4[0]; bf[2*np][1] = r4[1];
                bf[2*np+1][0] = r4[2]; bf[2*np+1][1] = r4[3];
            }
            #pragma unroll
            for (int mt = 0; mt < 4; mt++)
                #pragma unroll
                for (int nt = 0; nt < 8; nt++)
                    mma_f16(acc[mt][nt], af[mt], bf[nt]);
        }
        __syncthreads();
    }

    // Epilogue
    #pragma unroll
    for (int mt = 0; mt < 4; mt++) {
        #pragma unroll
        for (int nt = 0; nt < 8; nt++) {
            int r = bm + wm + mt * 16 + g;
            int c = bn + wn + nt * 8 + 2 * t;
            float b0 = bias[c], b1 = bias[c + 1];
            float v00 = acc[mt][nt][0] + b0;
            float v01 = acc[mt][nt][1] + b1;
            float v10 = acc[mt][nt][2] + b0;
            float v11 = acc[mt][nt][3] + b1;
            if (MODE == 1) {
                v00 = sigmoidf_(v00); v01 = sigmoidf_(v01);
                v10 = sigmoidf_(v10); v11 = sigmoidf_(v11);
            }
            if (MODE == 2) {
                float* C = (float*)Cout;
                float2 r0 = *(const float2*)&res[(size_t)r * N + c];
                float2 r1 = *(const float2*)&res[(size_t)(r + 8) * N + c];
                v00 += r0.x; v01 += r0.y; v10 += r1.x; v11 += r1.y;
                *(float2*)&C[(size_t)r * N + c]       = make_float2(v00, v01);
                *(float2*)&C[(size_t)(r + 8) * N + c] = make_float2(v10, v11);
            } else {
                __half* C = (__half*)Cout;
                *(__half2*)&C[(size_t)r * N + c]       = __floats2half2_rn(v00, v01);
                *(__half2*)&C[(size_t)(r + 8) * N + c] = __floats2half2_rn(v10, v11);
            }
        }
    }
}

// ---------------------------------------------------------------------------
// Chunked parallel scan (3 passes). p half, gate half, xn half, mixed half.
// ---------------------------------------------------------------------------
__global__ void scan_p1(const __half* __restrict__ p,
                        float* __restrict__ Ac, float* __restrict__ Hc,
                        int L, int CL) {
    int chain = blockIdx.x;
    int chunk = blockIdx.y;
    int b = chain / Hh;
    int h = chain % Hh;
    int s = threadIdx.x;

    const size_t pstr = (size_t)Hh * 3 * DSs;
    const __half* pb = p + ((size_t)b * L + (size_t)chunk * CL) * pstr
                         + (size_t)h * 3 * DSs + s;

    float A = 1.0f, hl = 0.0f;
    for (int l = 0; l < CL; l += 4) {
        float d0 = __half2float(__ldg(pb + (size_t)(l+0) * pstr));
        float d1 = __half2float(__ldg(pb + (size_t)(l+1) * pstr));
        float d2 = __half2float(__ldg(pb + (size_t)(l+2) * pstr));
        float d3 = __half2float(__ldg(pb + (size_t)(l+3) * pstr));
        float b0 = __half2float(__ldg(pb + (size_t)(l+0) * pstr + DSs));
        float b1 = __half2float(__ldg(pb + (size_t)(l+1) * pstr + DSs));
        float b2 = __half2float(__ldg(pb + (size_t)(l+2) * pstr + DSs));
        float b3 = __half2float(__ldg(pb + (size_t)(l+3) * pstr + DSs));
        float s0 = sigmoidf_(d0), s1 = sigmoidf_(d1);
        float s2 = sigmoidf_(d2), s3 = sigmoidf_(d3);
        A *= s0; hl = fmaf(s0, hl, b0);
        A *= s1; hl = fmaf(s1, hl, b1);
        A *= s2; hl = fmaf(s2, hl, b2);
        A *= s3; hl = fmaf(s3, hl, b3);
    }
    size_t idx = ((size_t)chain * NC + chunk) * DSs + s;
    Ac[idx] = A;
    Hc[idx] = hl;
}

__global__ void scan_mid(const float* __restrict__ Ac, const float* __restrict__ Hc,
                         const float* __restrict__ st0,
                         float* __restrict__ hin, float* __restrict__ hlast) {
    int chain = blockIdx.x;
    int s = threadIdx.x;
    float h = st0[(size_t)chain * DSs + s];
    #pragma unroll
    for (int c = 0; c < NC; c++) {
        size_t idx = ((size_t)chain * NC + c) * DSs + s;
        hin[idx] = h;
        h = fmaf(Ac[idx], h, Hc[idx]);
    }
    hlast[(size_t)chain * DSs + s] = h;
}

__global__ void scan_p3(const __half* __restrict__ p,
                        const __half* __restrict__ gate,
                        const __half* __restrict__ xn,
                        const float* __restrict__ hin,
                        __half* __restrict__ mixed, int L, int CL) {
    int chain = blockIdx.x;
    int chunk = blockIdx.y;
    int b = chain / Hh;
    int h = chain % Hh;
    int s = threadIdx.x;

    float hst = hin[((size_t)chain * NC + chunk) * DSs + s];

    const size_t pstr = (size_t)Hh * 3 * DSs;
    size_t l0 = (size_t)chunk * CL;
    const __half* pb = p + ((size_t)b * L + l0) * pstr + (size_t)h * 3 * DSs + s;
    size_t goff = ((size_t)b * L + l0) * Dm + (size_t)h * DSs + s;
    const __half* gb = gate + goff;
    const __half* xb = xn + goff;
    __half* mb = mixed + goff;

    for (int l = 0; l < CL; l += 4) {
        float dv[4], bv[4], cv[4], gv[4], xv[4];
        #pragma unroll
        for (int u = 0; u < 4; u++) {
            const __half* pp = pb + (size_t)(l + u) * pstr;
            dv[u] = __half2float(__ldg(pp));
            bv[u] = __half2float(__ldg(pp + DSs));
            cv[u] = __half2float(__ldg(pp + 2 * DSs));
            gv[u] = __half2float(__ldg(gb + (size_t)(l + u) * Dm));
            xv[u] = __half2float(__ldg(xb + (size_t)(l + u) * Dm));
        }
        #pragma unroll
        for (int u = 0; u < 4; u++) {
            float dsg = sigmoidf_(dv[u]);
            hst = fmaf(dsg, hst, bv[u]);
            float ssm = cv[u] * hst;
            mb[(size_t)(l + u) * Dm] = __float2half_rn(fmaf(gv[u], ssm - xv[u], xv[u]));
        }
    }
}

// ---------------------------------------------------------------------------
// Launch
// ---------------------------------------------------------------------------
extern "C" void kernel_launch(void* const* d_in, const int* in_sizes, int n_in,
                              void* d_out, int out_size) {
    const float* x      = (const float*)d_in[0];
    const float* state  = (const float*)d_in[1];
    const float* norm_w = (const float*)d_in[2];
    const float* conv_w = (const float*)d_in[3];
    const float* conv_b = (const float*)d_in[4];
    const float* pp_w   = (const float*)d_in[5];
    const float* pp_b   = (const float*)d_in[6];
    const float* gp_w   = (const float*)d_in[7];
    const float* gp_b   = (const float*)d_in[8];
    const float* op_w   = (const float*)d_in[9];
    const float* op_b   = (const float*)d_in[10];
    float* out = (float*)d_out;

    int BL = in_sizes[0] / Dm;                 // 8192
    int Bb = in_sizes[1] / (Hh * DSs);         // 2
    int L  = BL / Bb;                          // 4096
    int NBc = Bb * Hh;                         // 64
    int CL  = L / NC;                          // 64

    static bool attr_done = false;
    if (!attr_done) {
        cudaFuncSetAttribute(gemm_fp16<0>, cudaFuncAttributeMaxDynamicSharedMemorySize, GEMM_SMEM_BYTES);
        cudaFuncSetAttribute(gemm_fp16<1>, cudaFuncAttributeMaxDynamicSharedMemorySize, GEMM_SMEM_BYTES);
        cudaFuncSetAttribute(gemm_fp16<2>, cudaFuncAttributeMaxDynamicSharedMemorySize, GEMM_SMEM_BYTES);
        attr_done = true;
    }

    float* scratch;
    cudaGetSymbolAddress((void**)&scratch, g_scratch);
    __half* xnH   = (__half*)(scratch + OFF_XNH);
    __half* xcH   = (__half*)(scratch + OFF_XCH);
    __half* mxH   = (__half*)(scratch + OFF_MXH);
    __half* pH    = (__half*)(scratch + OFF_PH);
    __half* gateH = (__half*)(scratch + OFF_GATEH);
    float*  scanA = scratch + OFF_SCANA;
    float*  scanH = scratch + OFF_SCANH;
    float*  scanI = scratch + OFF_SCANI;
    __half* ppH   = (__half*)(scratch + OFF_PPH);
    __half* gpH   = (__half*)(scratch + OFF_GPH);
    __half* opH   = (__half*)(scratch + OFF_OPH);

    // 0) Weight transposes + fp16 round (single fused launch)
    transpose_half_all<<<dim3(P_COLS / 32, Dm / 32, 3), dim3(32, 8)>>>(
        pp_w, gp_w, op_w, ppH, gpH, opH);

    // 1) RMSNorm (fp16 xn)
    rmsnorm_kernel<<<BL, 256>>>(x, norm_w, xnH);

    // 2) Causal conv + SiLU (fp16 xc)
    conv_silu_kernel<<<dim3(Dm / 128, L / 256, Bb), 128>>>(xnH, conv_w, conv_b, xcH, L);

    // 3) p = xn @ pp_w + pp_b (fp16 out)
    gemm_fp16<0><<<dim3(P_COLS / 256, BL / 128), 256, GEMM_SMEM_BYTES>>>(
        xnH, ppH, pp_b, nullptr, pH, BL, P_COLS, Dm);

    // 4) gate = sigmoid(xc @ gp_w + gp_b) (fp16 out)
    gemm_fp16<1><<<dim3(Dm / 256, BL / 128), 256, GEMM_SMEM_BYTES>>>(
        xcH, gpH, gp_b, nullptr, gateH, BL, Dm, Dm);

    // 5) scan (3 passes); h_last to tail of output
    scan_p1<<<dim3(NBc, NC), DSs>>>(pH, scanA, scanH, L, CL);
    scan_mid<<<NBc, DSs>>>(scanA, scanH, state, scanI, out + (size_t)BL * Dm);
    scan_p3<<<dim3(NBc, NC), DSs>>>(pH, gateH, xnH, scanI, mxH, L, CL);

    // 6) y = mixed @ op_w + op_b + x (fp32 out)
    gemm_fp16<2><<<dim3(Dm / 256, BL / 128), 256, GEMM_SMEM_BYTES>>>(
        mxH, opH, op_b, x, out, BL, Dm, Dm);
}

// round 15
// speedup vs baseline: 1.1598x; 1.1598x over previous
#include <cuda_runtime.h>
#include <cuda_fp16.h>
#include <cstdint>
#include <cstddef>
#include <math.h>

// Problem constants
#define Dm   2048
#define Hh   32
#define DSs  64
#define KK   4
#define EPSf 1e-6f
#define NC   64            // scan chunks

// Max sizes (B=2, L=4096)
#define BL_MAX  8192
#define P_COLS  (3*Dm)   // 6144
#define NB_MAX  64       // B*H chains

// Scratch layout (in floats)
#define OFF_XNH    ((size_t)0)                               // half[BL*Dm]
#define OFF_XCH    (OFF_XNH + (size_t)BL_MAX*Dm/2)
#define OFF_MXH    (OFF_XCH + (size_t)BL_MAX*Dm/2)
#define OFF_PH     (OFF_MXH + (size_t)BL_MAX*Dm/2)           // half[BL*P_COLS]
#define OFF_GATEH  (OFF_PH  + (size_t)BL_MAX*P_COLS/2)       // half[BL*Dm]
#define OFF_SCANA  (OFF_GATEH + (size_t)BL_MAX*Dm/2)
#define OFF_SCANH  (OFF_SCANA + (size_t)NB_MAX*NC*DSs)
#define OFF_SCANI  (OFF_SCANH + (size_t)NB_MAX*NC*DSs)
#define OFF_PPH    (OFF_SCANI + (size_t)NB_MAX*NC*DSs)       // half[P_COLS*Dm]
#define OFF_GPH    (OFF_PPH + (size_t)P_COLS*Dm/2)
#define OFF_OPH    (OFF_GPH + (size_t)Dm*Dm/2)
#define SCRATCH_FLOATS (OFF_OPH + (size_t)Dm*Dm/2)

__device__ float g_scratch[SCRATCH_FLOATS];

// ---------------------------------------------------------------------------
// Helpers
// ---------------------------------------------------------------------------
__device__ __forceinline__ void mma_f16(float* c, const uint32_t* a, const uint32_t* b) {
    asm volatile(
        "mma.sync.aligned.m16n8k16.row.col.f32.f16.f16.f32 "
        "{%0,%1,%2,%3}, {%4,%5,%6,%7}, {%8,%9}, {%0,%1,%2,%3};\n"
        : "+f"(c[0]), "+f"(c[1]), "+f"(c[2]), "+f"(c[3])
        : "r"(a[0]), "r"(a[1]), "r"(a[2]), "r"(a[3]),
          "r"(b[0]), "r"(b[1]));
}

__device__ __forceinline__ void ldsm_x4(uint32_t* r, uint32_t addr) {
    asm volatile("ldmatrix.sync.aligned.m8n8.x4.shared.b16 {%0,%1,%2,%3}, [%4];"
        : "=r"(r[0]), "=r"(r[1]), "=r"(r[2]), "=r"(r[3]) : "r"(addr));
}

__device__ __forceinline__ void ldsm_x2(uint32_t* r, uint32_t addr) {
    asm volatile("ldmatrix.sync.aligned.m8n8.x2.shared.b16 {%0,%1}, [%2];"
        : "=r"(r[0]), "=r"(r[1]) : "r"(addr));
}

__device__ __forceinline__ void cp_async16(void* smem, const void* gmem) {
    uint32_t s = (uint32_t)__cvta_generic_to_shared(smem);
    asm volatile("cp.async.cg.shared.global [%0], [%1], 16;\n" :: "r"(s), "l"(gmem));
}

__device__ __forceinline__ float sigmoidf_(float v) {
    return 1.0f / (1.0f + __expf(-v));
}

__device__ __forceinline__ uint2 pack4h(float a, float b, float c, float d) {
    __half2 lo = __floats2half2_rn(a, b);
    __half2 hi = __floats2half2_rn(c, d);
    uint2 r;
    r.x = *(uint32_t*)&lo;
    r.y = *(uint32_t*)&hi;
    return r;
}

// ---------------------------------------------------------------------------
// Fused weight transpose + fp16 round for all three weights (z-indexed).
// ---------------------------------------------------------------------------
__global__ void transpose_half_all(const float* __restrict__ pp,
                                   const float* __restrict__ gp,
                                   const float* __restrict__ op,
                                   __half* __restrict__ ppT,
                                   __half* __restrict__ gpT,
                                   __half* __restrict__ opT) {
    const float* W;
    __half* WT;
    int N;
    if (blockIdx.z == 0)      { W = pp; WT = ppT; N = P_COLS; }
    else if (blockIdx.z == 1) { W = gp; WT = gpT; N = Dm; }
    else                      { W = op; WT = opT; N = Dm; }
    if (blockIdx.x * 32 >= N) return;

    __shared__ float t[32][33];
    int n0 = blockIdx.x * 32, k0 = blockIdx.y * 32;
    int tx = threadIdx.x, ty = threadIdx.y;
    #pragma unroll
    for (int i = 0; i < 4; i++)
        t[ty + 8*i][tx] = W[(size_t)(k0 + ty + 8*i) * N + n0 + tx];
    __syncthreads();
    int tid = ty * 32 + tx;
    int n_l = tid >> 3;
    int kq  = tid & 7;
    float a = t[kq*4 + 0][n_l];
    float b = t[kq*4 + 1][n_l];
    float c = t[kq*4 + 2][n_l];
    float d = t[kq*4 + 3][n_l];
    *(uint2*)&WT[(size_t)(n0 + n_l) * Dm + k0 + kq*4] = pack4h(a, b, c, d);
}

// ---------------------------------------------------------------------------
// RMSNorm (stores fp16 xn)
// ---------------------------------------------------------------------------
__global__ void rmsnorm_kernel(const float* __restrict__ x,
                               const float* __restrict__ w,
                               __half* __restrict__ xn) {
    size_t row = blockIdx.x;
    const float4* xr = (const float4*)(x + row * Dm);
    float4 v0 = xr[threadIdx.x];
    float4 v1 = xr[threadIdx.x + 256];
    float ss = v0.x*v0.x + v0.y*v0.y + v0.z*v0.z + v0.w*v0.w
             + v1.x*v1.x + v1.y*v1.y + v1.z*v1.z + v1.w*v1.w;
    #pragma unroll
    for (int o = 16; o > 0; o >>= 1) ss += __shfl_xor_sync(0xffffffffu, ss, o);
    __shared__ float red[8];
    if ((threadIdx.x & 31) == 0) red[threadIdx.x >> 5] = ss;
    __syncthreads();
    float tot = red[0] + red[1] + red[2] + red[3] + red[4] + red[5] + red[6] + red[7];
    float inv = rsqrtf(tot * (1.0f / Dm) + EPSf);

    const float4* wr = (const float4*)w;
    float4 w0 = wr[threadIdx.x];
    float4 w1 = wr[threadIdx.x + 256];
    uint2* orow = (uint2*)(xn + row * Dm);
    orow[threadIdx.x] = pack4h(v0.x * w0.x * inv, v0.y * w0.y * inv,
                               v0.z * w0.z * inv, v0.w * w0.w * inv);
    orow[threadIdx.x + 256] = pack4h(v1.x * w1.x * inv, v1.y * w1.y * inv,
                                     v1.z * w1.z * inv, v1.w * w1.w * inv);
}

// ---------------------------------------------------------------------------
// Causal depthwise conv (K=4) + SiLU (fp16 in, fp16 out; fp32 math)
// ---------------------------------------------------------------------------
__global__ void conv_silu_kernel(const __half* __restrict__ xn,
                                 const float* __restrict__ cw,
                                 const float* __restrict__ cb,
                                 __half* __restrict__ xc, int L) {
    int d  = blockIdx.x * 128 + threadIdx.x;
    int b  = blockIdx.z;
    int l0 = blockIdx.y * 256;
    float w0 = cw[d*KK + 0], w1 = cw[d*KK + 1], w2 = cw[d*KK + 2], w3 = cw[d*KK + 3];
    float bb = cb[d];
    const __half* base = xn + ((size_t)b * L) * Dm + d;
    __half* obase      = xc + ((size_t)b * L) * Dm + d;

    float xm3 = (l0 >= 3) ? __half2float(base[(size_t)(l0 - 3) * Dm]) : 0.0f;
    float xm2 = (l0 >= 2) ? __half2float(base[(size_t)(l0 - 2) * Dm]) : 0.0f;
    float xm1 = (l0 >= 1) ? __half2float(base[(size_t)(l0 - 1) * Dm]) : 0.0f;

    #pragma unroll 8
    for (int l = l0; l < l0 + 256; l++) {
        float xcur = __half2float(base[(size_t)l * Dm]);
        float acc = bb + w0 * xm3 + w1 * xm2 + w2 * xm1 + w3 * xcur;
        float sv = acc * sigmoidf_(acc);
        obase[(size_t)l * Dm] = __float2half_rn(sv);
        xm3 = xm2; xm2 = xm1; xm1 = xcur;
    }
}

// ---------------------------------------------------------------------------
// FP16 GEMM shared geometry: BM=128, BN=128, BK=64, warp tile 64x32,
// 256 threads, 3-stage cp.async pipeline, ONE __syncthreads per K-tile,
// 2 CTAs/SM.
// ---------------------------------------------------------------------------
#define FSTR 72                     // halves per SMEM row (72 mod 32 = 8)
#define TILE_H (128 * FSTR)         // 9216 halves per matrix tile
#define STG_HV (2 * TILE_H)         // A+B per stage
#define GEMM_SMEM_BYTES (3 * STG_HV * 2)   // 110592 B

#define GEMM_LOAD_STAGE(stg, k0)                                              \
    do {                                                                       \
        __half* dA = smh + (stg) * STG_HV;                                     \
        __half* dB = dA + TILE_H;                                              \
        _Pragma("unroll")                                                      \
        for (int i_ = 0; i_ < 4; i_++) {                                       \
            int r_ = l_r + 32 * i_;                                            \
            cp_async16(&dA[r_ * FSTR + l_c], Aptr + (size_t)r_ * K + (k0) + l_c); \
            cp_async16(&dB[r_ * FSTR + l_c], Bptr + (size_t)r_ * K + (k0) + l_c); \
        }                                                                      \
        asm volatile("cp.async.commit_group;\n" ::);                           \
    } while (0)

#define GEMM_MAINLOOP()                                                        \
    GEMM_LOAD_STAGE(0, 0);                                                     \
    GEMM_LOAD_STAGE(1, 64);                                                    \
    for (int kt = 0; kt < NK; kt++) {                                          \
        if (kt + 1 < NK) asm volatile("cp.async.wait_group 1;\n" ::);          \
        else             asm volatile("cp.async.wait_group 0;\n" ::);          \
        __syncthreads();                                                       \
        int ns = kt + 2;                                                       \
        if (ns < NK) { int s_ = ns % 3; GEMM_LOAD_STAGE(s_, ns * 64); }        \
        int rs = kt % 3;                                                       \
        uint32_t aBase = smBase + (uint32_t)((rs * STG_HV) * 2) + a_off;       \
        uint32_t bBase = smBase + (uint32_t)((rs * STG_HV + TILE_H) * 2) + b_off; \
        _Pragma("unroll")                                                      \
        for (int k16 = 0; k16 < 4; k16++) {                                    \
            uint32_t af[4][4], bf[4][2];                                       \
            _Pragma("unroll")                                                  \
            for (int mt = 0; mt < 4; mt++)                                     \
                ldsm_x4(af[mt], aBase + (uint32_t)(mt * 16 * FSTR * 2 + k16 * 32)); \
            _Pragma("unroll")                                                  \
            for (int nt = 0; nt < 4; nt++)                                     \
                ldsm_x2(bf[nt], bBase + (uint32_t)(nt * 8 * FSTR * 2 + k16 * 32)); \
            _Pragma("unroll")                                                  \
            for (int mt = 0; mt < 4; mt++)                                     \
                _Pragma("unroll")                                              \
                for (int nt = 0; nt < 4; nt++)                                 \
                    mma_f16(acc[mt][nt], af[mt], bf[nt]);                      \
        }                                                                      \
    }

// Fused p + gate GEMM: CTA column-block selects problem.
//   blockIdx.x <  48 -> p    = xn @ ppT + pp_b          (half out, N=6144)
//   blockIdx.x >= 48 -> gate = sigmoid(xc @ gpT + gp_b) (half out, N=2048)
__global__ __launch_bounds__(256, 2)
void gemm_pg(const __half* __restrict__ xn, const __half* __restrict__ xc,
             const __half* __restrict__ ppT, const __half* __restrict__ gpT,
             const float* __restrict__ pp_b, const float* __restrict__ gp_b,
             __half* __restrict__ pOut, __half* __restrict__ gOut, int K) {
    extern __shared__ __half smh[];

    int tid  = threadIdx.x;
    int wid  = tid >> 5;
    int lane = tid & 31;
    int wm = (wid & 1) * 64;
    int wn = (wid >> 1) * 32;
    int g = lane >> 2;
    int t = lane & 3;

    bool is_gate = (blockIdx.x >= 48);
    int bn = (is_gate ? (blockIdx.x - 48) : blockIdx.x) * 128;
    int N  = is_gate ? Dm : P_COLS;
    int bm = blockIdx.y * 128;

    const __half* Aptr = (is_gate ? xc : xn) + (size_t)bm * K;
    const __half* Bptr = (is_gate ? gpT : ppT) + (size_t)bn * K;
    const float* bias  = is_gate ? gp_b : pp_b;
    __half* C          = is_gate ? gOut : pOut;

    float acc[4][4][4];
    #pragma unroll
    for (int i = 0; i < 4; i++)
        #pragma unroll
        for (int j = 0; j < 4; j++)
            #pragma unroll
            for (int q = 0; q < 4; q++) acc[i][j][q] = 0.0f;

    int l_r = tid >> 3;            // 0..31
    int l_c = (tid & 7) * 8;       // 0..56 halves

    uint32_t smBase = (uint32_t)__cvta_generic_to_shared(&smh[0]);
    uint32_t a_off = (uint32_t)(((wm + (lane & 15)) * FSTR + ((lane >> 4) << 3)) * 2);
    uint32_t b_off = (uint32_t)(((wn + (lane & 7)) * FSTR + (((lane >> 3) & 1) << 3)) * 2);

    int NK = K / 64;
    GEMM_MAINLOOP();

    // Epilogue (half out)
    #pragma unroll
    for (int mt = 0; mt < 4; mt++) {
        #pragma unroll
        for (int nt = 0; nt < 4; nt++) {
            int r = bm + wm + mt * 16 + g;
            int c = bn + wn + nt * 8 + 2 * t;
            float b0 = bias[c], b1 = bias[c + 1];
            float v00 = acc[mt][nt][0] + b0;
            float v01 = acc[mt][nt][1] + b1;
            float v10 = acc[mt][nt][2] + b0;
            float v11 = acc[mt][nt][3] + b1;
            if (is_gate) {
                v00 = sigmoidf_(v00); v01 = sigmoidf_(v01);
                v10 = sigmoidf_(v10); v11 = sigmoidf_(v11);
            }
            *(__half2*)&C[(size_t)r * N + c]       = __floats2half2_rn(v00, v01);
            *(__half2*)&C[(size_t)(r + 8) * N + c] = __floats2half2_rn(v10, v11);
        }
    }
}

// Output GEMM: y = mixed @ opT + op_b + x (fp32 out)
__global__ __launch_bounds__(256, 2)
void gemm_out(const __half* __restrict__ A, const __half* __restrict__ BT,
              const float* __restrict__ bias, const float* __restrict__ res,
              float* __restrict__ C, int N, int K) {
    extern __shared__ __half smh[];

    int tid  = threadIdx.x;
    int wid  = tid >> 5;
    int lane = tid & 31;
    int wm = (wid & 1) * 64;
    int wn = (wid >> 1) * 32;
    int g = lane >> 2;
    int t = lane & 3;

    int bm = blockIdx.y * 128;
    int bn = blockIdx.x * 128;

    const __half* Aptr = A  + (size_t)bm * K;
    const __half* Bptr = BT + (size_t)bn * K;

    float acc[4][4][4];
    #pragma unroll
    for (int i = 0; i < 4; i++)
        #pragma unroll
        for (int j = 0; j < 4; j++)
            #pragma unroll
            for (int q = 0; q < 4; q++) acc[i][j][q] = 0.0f;

    int l_r = tid >> 3;
    int l_c = (tid & 7) * 8;

    uint32_t smBase = (uint32_t)__cvta_generic_to_shared(&smh[0]);
    uint32_t a_off = (uint32_t)(((wm + (lane & 15)) * FSTR + ((lane >> 4) << 3)) * 2);
    uint32_t b_off = (uint32_t)(((wn + (lane & 7)) * FSTR + (((lane >> 3) & 1) << 3)) * 2);

    int NK = K / 64;
    GEMM_MAINLOOP();

    #pragma unroll
    for (int mt = 0; mt < 4; mt++) {
        #pragma unroll
        for (int nt = 0; nt < 4; nt++) {
            int r = bm + wm + mt * 16 + g;
            int c = bn + wn + nt * 8 + 2 * t;
            float b0 = bias[c], b1 = bias[c + 1];
            float2 r0 = *(const float2*)&res[(size_t)r * N + c];
            float2 r1 = *(const float2*)&res[(size_t)(r + 8) * N + c];
            *(float2*)&C[(size_t)r * N + c] =
                make_float2(acc[mt][nt][0] + b0 + r0.x, acc[mt][nt][1] + b1 + r0.y);
            *(float2*)&C[(size_t)(r + 8) * N + c] =
                make_float2(acc[mt][nt][2] + b0 + r1.x, acc[mt][nt][3] + b1 + r1.y);
        }
    }
}

// ---------------------------------------------------------------------------
// Chunked parallel scan (3 passes). p half, gate half, xn half, mixed half.
// ---------------------------------------------------------------------------
__global__ void scan_p1(const __half* __restrict__ p,
                        float* __restrict__ Ac, float* __restrict__ Hc,
                        int L, int CL) {
    int chain = blockIdx.x;
    int chunk = blockIdx.y;
    int b = chain / Hh;
    int h = chain % Hh;
    int s = threadIdx.x;

    const size_t pstr = (size_t)Hh * 3 * DSs;
    const __half* pb = p + ((size_t)b * L + (size_t)chunk * CL) * pstr
                         + (size_t)h * 3 * DSs + s;

    float A = 1.0f, hl = 0.0f;
    for (int l = 0; l < CL; l += 4) {
        float d0 = __half2float(__ldg(pb + (size_t)(l+0) * pstr));
        float d1 = __half2float(__ldg(pb + (size_t)(l+1) * pstr));
        float d2 = __half2float(__ldg(pb + (size_t)(l+2) * pstr));
        float d3 = __half2float(__ldg(pb + (size_t)(l+3) * pstr));
        float b0 = __half2float(__ldg(pb + (size_t)(l+0) * pstr + DSs));
        float b1 = __half2float(__ldg(pb + (size_t)(l+1) * pstr + DSs));
        float b2 = __half2float(__ldg(pb + (size_t)(l+2) * pstr + DSs));
        float b3 = __half2float(__ldg(pb + (size_t)(l+3) * pstr + DSs));
        float s0 = sigmoidf_(d0), s1 = sigmoidf_(d1);
        float s2 = sigmoidf_(d2), s3 = sigmoidf_(d3);
        A *= s0; hl = fmaf(s0, hl, b0);
        A *= s1; hl = fmaf(s1, hl, b1);
        A *= s2; hl = fmaf(s2, hl, b2);
        A *= s3; hl = fmaf(s3, hl, b3);
    }
    size_t idx = ((size_t)chain * NC + chunk) * DSs + s;
    Ac[idx] = A;
    Hc[idx] = hl;
}

__global__ void scan_mid(const float* __restrict__ Ac, const float* __restrict__ Hc,
                         const float* __restrict__ st0,
                         float* __restrict__ hin, float* __restrict__ hlast) {
    int chain = blockIdx.x;
    int s = threadIdx.x;
    float h = st0[(size_t)chain * DSs + s];
    #pragma unroll
    for (int c = 0; c < NC; c++) {
        size_t idx = ((size_t)chain * NC + c) * DSs + s;
        hin[idx] = h;
        h = fmaf(Ac[idx], h, Hc[idx]);
    }
    hlast[(size_t)chain * DSs + s] = h;
}

__global__ void scan_p3(const __half* __restrict__ p,
                        const __half* __restrict__ gate,
                        const __half* __restrict__ xn,
                        const float* __restrict__ hin,
                        __half* __restrict__ mixed, int L, int CL) {
    int chain = blockIdx.x;
    int chunk = blockIdx.y;
    int b = chain / Hh;
    int h = chain % Hh;
    int s = threadIdx.x;

    float hst = hin[((size_t)chain * NC + chunk) * DSs + s];

    const size_t pstr = (size_t)Hh * 3 * DSs;
    size_t l0 = (size_t)chunk * CL;
    const __half* pb = p + ((size_t)b * L + l0) * pstr + (size_t)h * 3 * DSs + s;
    size_t goff = ((size_t)b * L + l0) * Dm + (size_t)h * DSs + s;
    const __half* gb = gate + goff;
    const __half* xb = xn + goff;
    __half* mb = mixed + goff;

    for (int l = 0; l < CL; l += 4) {
        float dv[4], bv[4], cv[4], gv[4], xv[4];
        #pragma unroll
        for (int u = 0; u < 4; u++) {
            const __half* pp = pb + (size_t)(l + u) * pstr;
            dv[u] = __half2float(__ldg(pp));
            bv[u] = __half2float(__ldg(pp + DSs));
            cv[u] = __half2float(__ldg(pp + 2 * DSs));
            gv[u] = __half2float(__ldg(gb + (size_t)(l + u) * Dm));
            xv[u] = __half2float(__ldg(xb + (size_t)(l + u) * Dm));
        }
        #pragma unroll
        for (int u = 0; u < 4; u++) {
            float dsg = sigmoidf_(dv[u]);
            hst = fmaf(dsg, hst, bv[u]);
            float ssm = cv[u] * hst;
            mb[(size_t)(l + u) * Dm] = __float2half_rn(fmaf(gv[u], ssm - xv[u], xv[u]));
        }
    }
}

// ---------------------------------------------------------------------------
// Launch
// ---------------------------------------------------------------------------
extern "C" void kernel_launch(void* const* d_in, const int* in_sizes, int n_in,
                              void* d_out, int out_size) {
    const float* x      = (const float*)d_in[0];
    const float* state  = (const float*)d_in[1];
    const float* norm_w = (const float*)d_in[2];
    const float* conv_w = (const float*)d_in[3];
    const float* conv_b = (const float*)d_in[4];
    const float* pp_w   = (const float*)d_in[5];
    const float* pp_b   = (const float*)d_in[6];
    const float* gp_w   = (const float*)d_in[7];
    const float* gp_b   = (const float*)d_in[8];
    const float* op_w   = (const float*)d_in[9];
    const float* op_b   = (const float*)d_in[10];
    float* out = (float*)d_out;

    int BL = in_sizes[0] / Dm;                 // 8192
    int Bb = in_sizes[1] / (Hh * DSs);         // 2
    int L  = BL / Bb;                          // 4096
    int NBc = Bb * Hh;                         // 64
    int CL  = L / NC;                          // 64

    static bool attr_done = false;
    if (!attr_done) {
        cudaFuncSetAttribute(gemm_pg,  cudaFuncAttributeMaxDynamicSharedMemorySize, GEMM_SMEM_BYTES);
        cudaFuncSetAttribute(gemm_out, cudaFuncAttributeMaxDynamicSharedMemorySize, GEMM_SMEM_BYTES);
        attr_done = true;
    }

    float* scratch;
    cudaGetSymbolAddress((void**)&scratch, g_scratch);
    __half* xnH   = (__half*)(scratch + OFF_XNH);
    __half* xcH   = (__half*)(scratch + OFF_XCH);
    __half* mxH   = (__half*)(scratch + OFF_MXH);
    __half* pH    = (__half*)(scratch + OFF_PH);
    __half* gateH = (__half*)(scratch + OFF_GATEH);
    float*  scanA = scratch + OFF_SCANA;
    float*  scanH = scratch + OFF_SCANH;
    float*  scanI = scratch + OFF_SCANI;
    __half* ppH   = (__half*)(scratch + OFF_PPH);
    __half* gpH   = (__half*)(scratch + OFF_GPH);
    __half* opH   = (__half*)(scratch + OFF_OPH);

    // 0) Weight transposes + fp16 round (single fused launch)
    transpose_half_all<<<dim3(P_COLS / 32, Dm / 32, 3), dim3(32, 8)>>>(
        pp_w, gp_w, op_w, ppH, gpH, opH);

    // 1) RMSNorm (fp16 xn)
    rmsnorm_kernel<<<BL, 256>>>(x, norm_w, xnH);

    // 2) Causal conv + SiLU (fp16 xc)
    conv_silu_kernel<<<dim3(Dm / 128, L / 256, Bb), 128>>>(xnH, conv_w, conv_b, xcH, L);

    // 3+4) Fused: p = xn @ pp_w + pp_b  AND  gate = sigmoid(xc @ gp_w + gp_b)
    gemm_pg<<<dim3(P_COLS / 128 + Dm / 128, BL / 128), 256, GEMM_SMEM_BYTES>>>(
        xnH, xcH, ppH, gpH, pp_b, gp_b, pH, gateH, Dm);

    // 5) scan (3 passes); h_last to tail of output
    scan_p1<<<dim3(NBc, NC), DSs>>>(pH, scanA, scanH, L, CL);
    scan_mid<<<NBc, DSs>>>(scanA, scanH, state, scanI, out + (size_t)BL * Dm);
    scan_p3<<<dim3(NBc, NC), DSs>>>(pH, gateH, xnH, scanI, mxH, L, CL);

    // 6) y = mixed @ op_w + op_b + x (fp32 out)
    gemm_out<<<dim3(Dm / 128, BL / 128), 256, GEMM_SMEM_BYTES>>>(
        mxH, opH, op_b, x, out, Dm, Dm);
}